// round 4
// baseline (speedup 1.0000x reference)
#include <cuda_runtime.h>

#define S_LEN 512
#define BATCH 2048
#define DIN 64
#define HID 128
#define NROWS (S_LEN * BATCH)          // 1M rows of U

typedef unsigned long long u64;

// 512 MB scratch for U = x @ W_ih^T + b_ih  (device global: no allocation)
__device__ float g_U[(size_t)NROWS * HID];

__device__ __forceinline__ u64 ffma2(u64 a, u64 b, u64 c) {
    u64 d;
    asm("fma.rn.f32x2 %0, %1, %2, %3;" : "=l"(d) : "l"(a), "l"(b), "l"(c));
    return d;
}
__device__ __forceinline__ u64 dup2(float v) {
    u64 d;
    asm("mov.b64 %0, {%1, %1};" : "=l"(d) : "f"(v));
    return d;
}
__device__ __forceinline__ u64 pack2(float lo, float hi) {
    u64 d;
    asm("mov.b64 %0, {%1, %2};" : "=l"(d) : "f"(lo), "f"(hi));
    return d;
}
__device__ __forceinline__ void unpack2(u64 v, float& lo, float& hi) {
    asm("mov.b64 {%0, %1}, %2;" : "=f"(lo), "=f"(hi) : "l"(v));
}
__device__ __forceinline__ float fast_tanh(float v) {
    float e = __expf(2.0f * v);
    return 1.0f - __fdividef(2.0f, e + 1.0f);
}

// ===================== Kernel 1: U = x @ W_ih^T + b_ih =====================
// 256 threads = 8 warps; each warp-iteration does 4 rows x 128 cols.

#define PC_THREADS 256
#define PC_GRID 592

struct __align__(16) PCSmem {
    float wih_t[DIN][HID];        // 32 KB transposed W_ih
    float xs[8][4][DIN];          // 8 KB per-warp x staging
};

__global__ void __launch_bounds__(PC_THREADS)
precompute_kernel(const float* __restrict__ x, const float* __restrict__ Wih,
                  const float* __restrict__ bih)
{
    __shared__ PCSmem s;
    const int tid  = threadIdx.x;
    const int warp = tid >> 5;
    const int lane = tid & 31;
    const int j0   = lane << 2;

    for (int idx = tid; idx < HID * DIN; idx += PC_THREADS) {
        int j = idx >> 6, k = idx & 63;
        s.wih_t[k][j] = Wih[idx];
    }
    const float4 bi4 = *(const float4*)(bih + j0);
    const u64 bi0 = pack2(bi4.x, bi4.y), bi1 = pack2(bi4.z, bi4.w);
    __syncthreads();

    for (int rowBlk = blockIdx.x * 32; rowBlk < NROWS; rowBlk += PC_GRID * 32) {
        const int warpRow = rowBlk + warp * 4;

        // stage 4 rows x 64 floats of x
        {
            const float4* p = (const float4*)(x + (size_t)warpRow * DIN);
            float4* xs4 = (float4*)&s.xs[warp][0][0];
            xs4[lane] = p[lane]; xs4[lane + 32] = p[lane + 32];
        }
        __syncwarp();

        u64 acc0[4], acc1[4];
        #pragma unroll
        for (int r = 0; r < 4; ++r) { acc0[r] = bi0; acc1[r] = bi1; }

        #pragma unroll 2
        for (int k4 = 0; k4 < DIN / 4; ++k4) {
            float xv[4][4];
            #pragma unroll
            for (int r = 0; r < 4; ++r)
                *(float4*)xv[r] = *(const float4*)&s.xs[warp][r][k4 * 4];
            #pragma unroll
            for (int kk = 0; kk < 4; ++kk) {
                const u64* w = (const u64*)&s.wih_t[k4 * 4 + kk][j0];
                const u64 w0 = w[0], w1 = w[1];
                #pragma unroll
                for (int r = 0; r < 4; ++r) {
                    const u64 xd = dup2(xv[r][kk]);
                    acc0[r] = ffma2(xd, w0, acc0[r]);
                    acc1[r] = ffma2(xd, w1, acc1[r]);
                }
            }
        }
        #pragma unroll
        for (int r = 0; r < 4; ++r) {
            float v0, v1, v2, v3;
            unpack2(acc0[r], v0, v1);
            unpack2(acc1[r], v2, v3);
            *(float4*)&g_U[(size_t)(warpRow + r) * HID + j0] =
                make_float4(v0, v1, v2, v3);
        }
        __syncwarp();
    }
}

// ===================== Kernel 2: recurrence (GEMM2 only) ====================
// 256 threads = 8 warps = 4 pairs. Pair p owns 4 batch rows; within a pair,
// warp half 0 owns cols 0..63, half 1 owns cols 64..127 (2 cols/lane).
// Only `a` (dup-staged) crosses warps; h and U are column-local.

#define L_THREADS 256
#define RPP 4                     // rows per pair
#define RPC 16                    // rows per CTA (4 pairs)
#define NCTA (BATCH / RPC)        // 128

struct __align__(16) LSmem {
    float whh_t[HID][HID];        // 64 KB transposed W_hh
    float adup[2][4][RPP][2 * HID];  // 32 KB duplicated-a staging, double buf
};

__global__ void __launch_bounds__(L_THREADS, 1)
loop_kernel(const float* __restrict__ h0, const float* __restrict__ bhh,
            const float* __restrict__ Whh, float* __restrict__ out)
{
    extern __shared__ LSmem s[];
    const int tid  = threadIdx.x;
    const int warp = tid >> 5;
    const int lane = tid & 31;
    const int pair = warp >> 1;
    const int half = warp & 1;
    const int j0   = half * 64 + lane * 2;      // this lane's 2 cols
    const int rows0 = blockIdx.x * RPC + pair * RPP;

    for (int idx = tid; idx < HID * HID; idx += L_THREADS) {
        int j = idx >> 7, k = idx & 127;
        s->whh_t[k][j] = Whh[idx];
    }

    const u64 bh = pack2(bhh[j0], bhh[j0 + 1]);

    float h[RPP][2];
    #pragma unroll
    for (int r = 0; r < RPP; ++r) {
        float2 hv = *(const float2*)(h0 + (size_t)(rows0 + r) * HID + j0);
        h[r][0] = hv.x; h[r][1] = hv.y;
    }

    // prefetch U(t=0)
    float2 Ur[RPP];
    #pragma unroll
    for (int r = 0; r < RPP; ++r)
        Ur[r] = *(const float2*)&g_U[(size_t)(rows0 + r) * HID + j0];

    __syncthreads();

    for (int t = 0; t < S_LEN; ++t) {
        const int buf = t & 1;

        // ---- a = U_t * h ; stage duplicated (one STS.128 per row) ----
        float a[RPP][2];
        #pragma unroll
        for (int r = 0; r < RPP; ++r) {
            a[r][0] = Ur[r].x * h[r][0];
            a[r][1] = Ur[r].y * h[r][1];
            *(float4*)&s->adup[buf][pair][r][2 * j0] =
                make_float4(a[r][0], a[r][0], a[r][1], a[r][1]);
        }

        // ---- prefetch U(t+1) ----
        {
            const int tn = (t + 1 < S_LEN) ? t + 1 : t;
            #pragma unroll
            for (int r = 0; r < RPP; ++r)
                Ur[r] = *(const float2*)
                    &g_U[((size_t)tn * BATCH + rows0 + r) * HID + j0];
        }
        __syncthreads();   // adup[buf] complete across the pair

        // ---- GEMM2: acc = a @ W_hh^T + b_hh  (this lane's 2 cols) ----
        u64 acc[RPP];
        #pragma unroll
        for (int r = 0; r < RPP; ++r) acc[r] = bh;

        const float* arow = &s->adup[buf][pair][0][0];
        #pragma unroll 8
        for (int k = 0; k < HID; k += 2) {
            const u64 w0 = *(const u64*)&s->whh_t[k][j0];
            const u64 w1 = *(const u64*)&s->whh_t[k + 1][j0];
            #pragma unroll
            for (int r = 0; r < RPP; ++r) {
                const u64* ad = (const u64*)(arow + r * (2 * HID) + 2 * k);
                acc[r] = ffma2(ad[0], w0, acc[r]);
                acc[r] = ffma2(ad[1], w1, acc[r]);
            }
        }

        // ---- h' = tanh(a + acc * h) ----
        #pragma unroll
        for (int r = 0; r < RPP; ++r) {
            float s0, s1;
            unpack2(acc[r], s0, s1);
            h[r][0] = fast_tanh(fmaf(s0, h[r][0], a[r][0]));
            h[r][1] = fast_tanh(fmaf(s1, h[r][1], a[r][1]));
        }
    }

    #pragma unroll
    for (int r = 0; r < RPP; ++r)
        *(float2*)(out + (size_t)(rows0 + r) * HID + j0) =
            make_float2(h[r][0], h[r][1]);
}

// ============================== launch =====================================

extern "C" void kernel_launch(void* const* d_in, const int* in_sizes, int n_in,
                              void* d_out, int out_size)
{
    const float* x   = (const float*)d_in[0];
    const float* h0  = (const float*)d_in[1];
    const float* Wih = (const float*)d_in[2];
    const float* bih = (const float*)d_in[3];
    const float* Whh = (const float*)d_in[4];
    const float* bhh = (const float*)d_in[5];

    precompute_kernel<<<PC_GRID, PC_THREADS>>>(x, Wih, bih);

    cudaFuncSetAttribute(loop_kernel, cudaFuncAttributeMaxDynamicSharedMemorySize,
                         (int)sizeof(LSmem));
    loop_kernel<<<NCTA, L_THREADS, sizeof(LSmem)>>>(h0, bhh, Whh, (float*)d_out);
}

// round 5
// speedup vs baseline: 1.6406x; 1.6406x over previous
#include <cuda_runtime.h>
#include <cuda_bf16.h>
#include <cstdint>

#define S_LEN 512
#define BATCH 2048
#define DIN 64
#define HID 128
#define NROWS (S_LEN * BATCH)

typedef unsigned long long u64;

// 512 MB scratch for U = x @ W_ih^T + b_ih
__device__ float g_U[(size_t)NROWS * HID];

__device__ __forceinline__ u64 ffma2(u64 a, u64 b, u64 c) {
    u64 d;
    asm("fma.rn.f32x2 %0, %1, %2, %3;" : "=l"(d) : "l"(a), "l"(b), "l"(c));
    return d;
}
__device__ __forceinline__ u64 dup2(float v) {
    u64 d; asm("mov.b64 %0, {%1, %1};" : "=l"(d) : "f"(v)); return d;
}
__device__ __forceinline__ u64 pack2(float lo, float hi) {
    u64 d; asm("mov.b64 %0, {%1, %2};" : "=l"(d) : "f"(lo), "f"(hi)); return d;
}
__device__ __forceinline__ void unpack2(u64 v, float& lo, float& hi) {
    asm("mov.b64 {%0, %1}, %2;" : "=f"(lo), "=f"(hi) : "l"(v));
}
__device__ __forceinline__ float fast_tanh(float v) {
    float e = __expf(2.0f * v);
    return 1.0f - __fdividef(2.0f, e + 1.0f);
}

// ===================== Kernel 1: U = x @ W_ih^T + b_ih (proven, at floor) ===
#define PC_THREADS 256
#define PC_GRID 592

struct __align__(16) PCSmem {
    float wih_t[DIN][HID];
    float xs[8][4][DIN];
};

__global__ void __launch_bounds__(PC_THREADS)
precompute_kernel(const float* __restrict__ x, const float* __restrict__ Wih,
                  const float* __restrict__ bih)
{
    __shared__ PCSmem s;
    const int tid  = threadIdx.x;
    const int warp = tid >> 5;
    const int lane = tid & 31;
    const int j0   = lane << 2;

    for (int idx = tid; idx < HID * DIN; idx += PC_THREADS) {
        int j = idx >> 6, k = idx & 63;
        s.wih_t[k][j] = Wih[idx];
    }
    const float4 bi4 = *(const float4*)(bih + j0);
    const u64 bi0 = pack2(bi4.x, bi4.y), bi1 = pack2(bi4.z, bi4.w);
    __syncthreads();

    for (int rowBlk = blockIdx.x * 32; rowBlk < NROWS; rowBlk += PC_GRID * 32) {
        const int warpRow = rowBlk + warp * 4;
        {
            const float4* p = (const float4*)(x + (size_t)warpRow * DIN);
            float4* xs4 = (float4*)&s.xs[warp][0][0];
            xs4[lane] = p[lane]; xs4[lane + 32] = p[lane + 32];
        }
        __syncwarp();

        u64 acc0[4], acc1[4];
        #pragma unroll
        for (int r = 0; r < 4; ++r) { acc0[r] = bi0; acc1[r] = bi1; }

        #pragma unroll 2
        for (int k4 = 0; k4 < DIN / 4; ++k4) {
            float xv[4][4];
            #pragma unroll
            for (int r = 0; r < 4; ++r)
                *(float4*)xv[r] = *(const float4*)&s.xs[warp][r][k4 * 4];
            #pragma unroll
            for (int kk = 0; kk < 4; ++kk) {
                const u64* w = (const u64*)&s.wih_t[k4 * 4 + kk][j0];
                const u64 w0 = w[0], w1 = w[1];
                #pragma unroll
                for (int r = 0; r < 4; ++r) {
                    const u64 xd = dup2(xv[r][kk]);
                    acc0[r] = ffma2(xd, w0, acc0[r]);
                    acc1[r] = ffma2(xd, w1, acc1[r]);
                }
            }
        }
        #pragma unroll
        for (int r = 0; r < 4; ++r) {
            float v0, v1, v2, v3;
            unpack2(acc0[r], v0, v1);
            unpack2(acc1[r], v2, v3);
            *(float4*)&g_U[(size_t)(warpRow + r) * HID + j0] =
                make_float4(v0, v1, v2, v3);
        }
        __syncwarp();
    }
}

// ===================== Kernel 2: recurrence via mma.sync bf16 ==============
// CTA = 16 batch rows, 4 warps; warp owns 32 output cols (4 n-tiles of 8).
// P = a @ W_hh^T with 3-way bf16 splits, 6 products (err ~2^-25/step).

#define ROWE 136                 // padded row (bf16 elems) -> 272 B
#define ROWB 272
#define WSPL (HID * ROWB)        // 34816 B per W split
#define ASPL (16 * ROWB)         // 4352 B per A split
#define ABUF (3 * ASPL)          // 13056 B
#define SM_W 0
#define SM_A (3 * WSPL)          // 104448
#define L_SMEM (SM_A + 2 * ABUF) // 130560 B

__device__ __forceinline__ void ldsm4(uint32_t r[4], uint32_t addr) {
    asm volatile("ldmatrix.sync.aligned.m8n8.x4.shared.b16 {%0,%1,%2,%3}, [%4];"
                 : "=r"(r[0]), "=r"(r[1]), "=r"(r[2]), "=r"(r[3]) : "r"(addr));
}
__device__ __forceinline__ void mma_bf16(float d[4], const uint32_t a[4],
                                         const uint32_t b0, const uint32_t b1) {
    asm volatile("mma.sync.aligned.m16n8k16.row.col.f32.bf16.bf16.f32 "
                 "{%0,%1,%2,%3}, {%4,%5,%6,%7}, {%8,%9}, {%0,%1,%2,%3};"
                 : "+f"(d[0]), "+f"(d[1]), "+f"(d[2]), "+f"(d[3])
                 : "r"(a[0]), "r"(a[1]), "r"(a[2]), "r"(a[3]), "r"(b0), "r"(b1));
}

__global__ void __launch_bounds__(128, 1)
loop_kernel(const float* __restrict__ h0, const float* __restrict__ bhh,
            const float* __restrict__ Whh, float* __restrict__ out)
{
    extern __shared__ unsigned char smem[];
    uint32_t smem_b;
    asm("{ .reg .u64 t; cvta.to.shared.u64 t, %1; cvt.u32.u64 %0, t; }"
        : "=r"(smem_b) : "l"(smem));

    const int tid  = threadIdx.x;
    const int warp = tid >> 5;
    const int lane = tid & 31;
    const int g    = lane >> 2;      // 0..7
    const int tq   = lane & 3;       // 0..3
    const int rowBase = blockIdx.x * 16;
    const int colW = warp * 32;

    // ---- split W_hh (row-major [n][k]) into 3 bf16 planes in smem ----
    for (int idx = tid; idx < HID * HID; idx += 128) {
        const int n = idx >> 7, k = idx & 127;
        float w = Whh[idx];
        __nv_bfloat16 w0 = __float2bfloat16(w);
        float r1 = w - __bfloat162float(w0);
        __nv_bfloat16 w1 = __float2bfloat16(r1);
        float r2 = r1 - __bfloat162float(w1);
        __nv_bfloat16 w2 = __float2bfloat16(r2);
        const size_t off = (size_t)n * ROWB + (size_t)k * 2;
        *(__nv_bfloat16*)(smem + SM_W + 0 * WSPL + off) = w0;
        *(__nv_bfloat16*)(smem + SM_W + 1 * WSPL + off) = w1;
        *(__nv_bfloat16*)(smem + SM_W + 2 * WSPL + off) = w2;
    }

    // ---- per-lane bias ----
    float bh0[4], bh1[4];
    #pragma unroll
    for (int nt = 0; nt < 4; ++nt) {
        bh0[nt] = bhh[colW + nt * 8 + tq * 2];
        bh1[nt] = bhh[colW + nt * 8 + tq * 2 + 1];
    }

    // ---- h, a in registers (rows {g, g+8}, warp's 32 cols) ----
    float h[2][4][2], a[2][4][2];
    #pragma unroll
    for (int r = 0; r < 2; ++r) {
        const int row = rowBase + g + 8 * r;
        #pragma unroll
        for (int nt = 0; nt < 4; ++nt) {
            float2 hv = *(const float2*)&h0[(size_t)row * HID + colW + nt * 8 + tq * 2];
            h[r][nt][0] = hv.x; h[r][nt][1] = hv.y;
            float2 uv = *(const float2*)&g_U[(size_t)row * HID + colW + nt * 8 + tq * 2];
            a[r][nt][0] = uv.x * hv.x; a[r][nt][1] = uv.y * hv.y;
        }
    }

    // a-split store helper offsets (local rows 0..15)
    const uint32_t abase = smem_b + SM_A;
    // store a(0) into buf 0
    #pragma unroll
    for (int r = 0; r < 2; ++r) {
        const int lrow = g + 8 * r;
        #pragma unroll
        for (int nt = 0; nt < 4; ++nt) {
            float v0 = a[r][nt][0], v1 = a[r][nt][1];
            __nv_bfloat16 s00 = __float2bfloat16(v0);
            __nv_bfloat16 s10 = __float2bfloat16(v1);
            float q0 = v0 - __bfloat162float(s00);
            float q1 = v1 - __bfloat162float(s10);
            __nv_bfloat16 s01 = __float2bfloat16(q0);
            __nv_bfloat16 s11 = __float2bfloat16(q1);
            __nv_bfloat16 s02 = __float2bfloat16(q0 - __bfloat162float(s01));
            __nv_bfloat16 s12 = __float2bfloat16(q1 - __bfloat162float(s11));
            const size_t o = (size_t)lrow * ROWB + (size_t)(colW + nt * 8 + tq * 2) * 2;
            *(__nv_bfloat162*)(smem + SM_A + 0 * ASPL + o) = __halves2bfloat162(s00, s10);
            *(__nv_bfloat162*)(smem + SM_A + 1 * ASPL + o) = __halves2bfloat162(s01, s11);
            *(__nv_bfloat162*)(smem + SM_A + 2 * ASPL + o) = __halves2bfloat162(s02, s12);
        }
    }
    __syncthreads();

    // ---- ldmatrix per-lane offsets ----
    const int q  = lane >> 3;     // quadrant 0..3
    const int lr = lane & 7;
    // A frags: rows (lr + (q&1)*8), k-offset +8 elems if q>=2
    const uint32_t a_off = (uint32_t)((lr + (q & 1) * 8) * ROWB + ((q & 2) ? 8 : 0) * 2);
    // B frags: W rows (colW + lr + 8 if q>=2), k-offset +8 if q odd
    const uint32_t b_off0 = smem_b + SM_W +
        (uint32_t)((colW + lr + ((q & 2) ? 8 : 0)) * ROWB + ((q & 1) ? 8 : 0) * 2);

    for (int t = 0; t < S_LEN; ++t) {
        const int buf = t & 1;

        // ---- prefetch U(t+1) ----
        const int tn = (t + 1 < S_LEN) ? t + 1 : t;
        float2 Un[2][4];
        #pragma unroll
        for (int r = 0; r < 2; ++r) {
            const size_t rb = ((size_t)tn * BATCH + rowBase + g + 8 * r) * HID;
            #pragma unroll
            for (int nt = 0; nt < 4; ++nt)
                Un[r][nt] = *(const float2*)&g_U[rb + colW + nt * 8 + tq * 2];
        }

        // ---- mma phase: P = a @ W^T (+bias), split products ----
        float De[4][4], Do[4][4];
        #pragma unroll
        for (int nt = 0; nt < 4; ++nt) {
            De[nt][0] = bh0[nt]; De[nt][1] = bh1[nt];
            De[nt][2] = bh0[nt]; De[nt][3] = bh1[nt];
            Do[nt][0] = Do[nt][1] = Do[nt][2] = Do[nt][3] = 0.0f;
        }

        const uint32_t abuf = abase + (uint32_t)buf * ABUF + a_off;
        #pragma unroll
        for (int ks = 0; ks < 8; ++ks) {
            uint32_t A0[4], A1[4], A2[4];
            ldsm4(A0, abuf + 0 * ASPL + ks * 32);
            ldsm4(A1, abuf + 1 * ASPL + ks * 32);
            ldsm4(A2, abuf + 2 * ASPL + ks * 32);

            uint32_t B[3][4];   // [split][ntile pair: b0(nt),b1(nt),b0(nt+1),b1(nt+1)] x2 pairs
            #pragma unroll
            for (int np = 0; np < 2; ++np) {
                #pragma unroll
                for (int s = 0; s < 3; ++s)
                    ldsm4(B[s], b_off0 + (uint32_t)s * WSPL +
                                (uint32_t)np * 16 * ROWB + ks * 32);
                #pragma unroll
                for (int half = 0; half < 2; ++half) {
                    const int nt = np * 2 + half;
                    const uint32_t b00 = B[0][2 * half], b01 = B[0][2 * half + 1];
                    const uint32_t b10 = B[1][2 * half], b11 = B[1][2 * half + 1];
                    const uint32_t b20 = B[2][2 * half], b21 = B[2][2 * half + 1];
                    mma_bf16(De[nt], A0, b00, b01);   // a0*W0
                    mma_bf16(Do[nt], A0, b10, b11);   // a0*W1
                    mma_bf16(Do[nt], A1, b00, b01);   // a1*W0
                    mma_bf16(De[nt], A1, b10, b11);   // a1*W1
                    mma_bf16(De[nt], A2, b00, b01);   // a2*W0
                    mma_bf16(Do[nt], A0, b20, b21);   // a0*W2
                }
            }
        }

        // ---- epilogue: h' = tanh(a + P*h); a_next = U(t+1)*h' ; store splits
        #pragma unroll
        for (int r = 0; r < 2; ++r) {
            const int lrow = g + 8 * r;
            #pragma unroll
            for (int nt = 0; nt < 4; ++nt) {
                float P0 = De[nt][2 * r + 0] + Do[nt][2 * r + 0];
                float P1 = De[nt][2 * r + 1] + Do[nt][2 * r + 1];
                float h0n = fast_tanh(fmaf(P0, h[r][nt][0], a[r][nt][0]));
                float h1n = fast_tanh(fmaf(P1, h[r][nt][1], a[r][nt][1]));
                h[r][nt][0] = h0n; h[r][nt][1] = h1n;
                float v0 = Un[r][nt].x * h0n;
                float v1 = Un[r][nt].y * h1n;
                a[r][nt][0] = v0; a[r][nt][1] = v1;

                __nv_bfloat16 s00 = __float2bfloat16(v0);
                __nv_bfloat16 s10 = __float2bfloat16(v1);
                float q0 = v0 - __bfloat162float(s00);
                float q1 = v1 - __bfloat162float(s10);
                __nv_bfloat16 s01 = __float2bfloat16(q0);
                __nv_bfloat16 s11 = __float2bfloat16(q1);
                __nv_bfloat16 s02 = __float2bfloat16(q0 - __bfloat162float(s01));
                __nv_bfloat16 s12 = __float2bfloat16(q1 - __bfloat162float(s11));
                const size_t o = (size_t)(buf ^ 1) * ABUF + (size_t)lrow * ROWB +
                                 (size_t)(colW + nt * 8 + tq * 2) * 2;
                *(__nv_bfloat162*)(smem + SM_A + 0 * ASPL + o) = __halves2bfloat162(s00, s10);
                *(__nv_bfloat162*)(smem + SM_A + 1 * ASPL + o) = __halves2bfloat162(s01, s11);
                *(__nv_bfloat162*)(smem + SM_A + 2 * ASPL + o) = __halves2bfloat162(s02, s12);
            }
        }
        __syncthreads();
    }

    // ---- write final hidden state ----
    #pragma unroll
    for (int r = 0; r < 2; ++r) {
        const int row = rowBase + g + 8 * r;
        #pragma unroll
        for (int nt = 0; nt < 4; ++nt)
            *(float2*)&out[(size_t)row * HID + colW + nt * 8 + tq * 2] =
                make_float2(h[r][nt][0], h[r][nt][1]);
    }
}

// ============================== launch =====================================

extern "C" void kernel_launch(void* const* d_in, const int* in_sizes, int n_in,
                              void* d_out, int out_size)
{
    const float* x   = (const float*)d_in[0];
    const float* h0  = (const float*)d_in[1];
    const float* Wih = (const float*)d_in[2];
    const float* bih = (const float*)d_in[3];
    const float* Whh = (const float*)d_in[4];
    const float* bhh = (const float*)d_in[5];

    precompute_kernel<<<PC_GRID, PC_THREADS>>>(x, Wih, bih);

    cudaFuncSetAttribute(loop_kernel, cudaFuncAttributeMaxDynamicSharedMemorySize,
                         L_SMEM);
    loop_kernel<<<BATCH / 16, 128, L_SMEM>>>(h0, bhh, Whh, (float*)d_out);
}